// round 13
// baseline (speedup 1.0000x reference)
#include <cuda_runtime.h>
#include <cuda_fp16.h>
#include <cstdint>

// Problem constants (fixed shapes for GLiNERLinkerPooler_14671608283278)
#define L_TOK 2048
#define H_DIM 768
#define W_NUM 1024
#define C_NUM 64
#define TH_DIM 1536   // 2*H
// W1 is (2304, 768): rows [0,768)=W1_t, [768,1536)=W1_l, [1536,2304)=W1_p

// ---------------- device scratch (no allocations allowed) ----------------
__device__ int      g_winner[W_NUM];
__device__ unsigned g_qhead;
__device__ __half   g_weh[W_NUM * H_DIM];
__device__ __half   g_WtokT[TH_DIM * H_DIM];      // half(W_tok^T) [n][k]
__device__ __half   g_W1tT[H_DIM * H_DIM];        // half(W1_t^T)  [n][k]
__device__ __half   g_W1pTh[H_DIM * H_DIM];       // half(W1_p^T)  [j][h]
__device__ __half   g_t01h[W_NUM * TH_DIM];       // half(t) [w][2H]
__device__ float    g_lb[C_NUM * TH_DIM];
__device__ __half   g_Ath[W_NUM * H_DIM];         // half(t0@W1_t + b1) [w][j]
__device__ float    g_Al[C_NUM * H_DIM];

// ---------------- helpers -------------------------------------------------
__device__ __forceinline__ void mma_f16(float* c, const uint32_t* a,
                                        uint32_t b0, uint32_t b1) {
    asm volatile(
        "mma.sync.aligned.m16n8k16.row.col.f32.f16.f16.f32 "
        "{%0,%1,%2,%3}, {%4,%5,%6,%7}, {%8,%9}, {%0,%1,%2,%3};"
        : "+f"(c[0]), "+f"(c[1]), "+f"(c[2]), "+f"(c[3])
        : "r"(a[0]), "r"(a[1]), "r"(a[2]), "r"(a[3]), "r"(b0), "r"(b1));
}
__device__ __forceinline__ uint32_t smem_u32(const void* p) {
    uint32_t a;
    asm("{ .reg .u64 t; cvta.to.shared.u64 t, %1; cvt.u32.u64 %0, t; }" : "=r"(a) : "l"(p));
    return a;
}
__device__ __forceinline__ void cpasync16(uint32_t dst, const void* src) {
    asm volatile("cp.async.cg.shared.global [%0], [%1], 16;" :: "r"(dst), "l"(src));
}
__device__ __forceinline__ uint32_t hmul2u(uint32_t a, uint32_t s) {
    __half2 r = __hmul2(*reinterpret_cast<__half2*>(&a), *reinterpret_cast<__half2*>(&s));
    return *reinterpret_cast<uint32_t*>(&r);
}
#define CP_COMMIT()  asm volatile("cp.async.commit_group;" ::: "memory")
#define CP_WAIT1()   asm volatile("cp.async.wait_group 1;" ::: "memory")
#define CP_WAIT2()   asm volatile("cp.async.wait_group 2;" ::: "memory")

// ---------------- scatter pooling (last token index wins) ----------------
__global__ void k_init_winner() {
    int w = blockIdx.x * blockDim.x + threadIdx.x;
    if (w < W_NUM) g_winner[w] = -1;
    if (w == 0) g_qhead = 0;                      // reset work queue each launch
}
__global__ void k_scatter(const int* __restrict__ wmask) {
    int l = blockIdx.x * blockDim.x + threadIdx.x;
    if (l < L_TOK) {
        int v = wmask[l];
        if (v > 0 && v - 1 < W_NUM) atomicMax(&g_winner[v - 1], l);
    }
}
__global__ void k_build_we_h(const float* __restrict__ tok_embs) {
    int w = blockIdx.x;
    int src = g_winner[w];
    __half* dst = &g_weh[w * H_DIM];
    if (src >= 0) {
        const float* s = &tok_embs[(size_t)src * H_DIM];
        for (int h = threadIdx.x; h < H_DIM; h += blockDim.x) dst[h] = __float2half(s[h]);
    } else {
        for (int h = threadIdx.x; h < H_DIM; h += blockDim.x) dst[h] = __float2half(0.0f);
    }
}

// ---------------- transpose: fp32 src[K][N] -> half dst[N][K] -------------
__global__ void k_transpose_h(const float* __restrict__ src, __half* __restrict__ dst,
                              int K, int N) {
    __shared__ float tl[32][33];
    int n0 = blockIdx.x * 32, k0 = blockIdx.y * 32;
    for (int dy = threadIdx.y; dy < 32; dy += 8)
        tl[dy][threadIdx.x] = src[(size_t)(k0 + dy) * N + n0 + threadIdx.x];
    __syncthreads();
    for (int dy = threadIdx.y; dy < 32; dy += 8)
        dst[(size_t)(n0 + dy) * K + k0 + threadIdx.x] = __float2half(tl[threadIdx.x][dy]);
}

// ---------------- SIMT fp32 GEMM (small label-side GEMMs only) ------------
__global__ void k_gemm_bias(const float* __restrict__ A, int lda,
                            const float* __restrict__ B, int ldb,
                            const float* __restrict__ bias,
                            float* __restrict__ C, int ldc, int K) {
    __shared__ float As[16][64];
    __shared__ float Bs[16][64];
    const int tid = threadIdx.x;
    const int tx = tid & 15;
    const int ty = tid >> 4;
    const int mbase = blockIdx.x * 64;
    const int nbase = blockIdx.y * 64;

    float acc[4][4] = {};
    const int lw = tid >> 2, lkq = tid & 3;
    const int lkk = tid >> 4, lj4 = tid & 15;

    for (int k0 = 0; k0 < K; k0 += 16) {
        float4 va = *reinterpret_cast<const float4*>(&A[(size_t)(mbase + lw) * lda + k0 + lkq * 4]);
        As[lkq * 4 + 0][lw] = va.x;
        As[lkq * 4 + 1][lw] = va.y;
        As[lkq * 4 + 2][lw] = va.z;
        As[lkq * 4 + 3][lw] = va.w;
        *reinterpret_cast<float4*>(&Bs[lkk][lj4 * 4]) =
            *reinterpret_cast<const float4*>(&B[(size_t)(k0 + lkk) * ldb + nbase + lj4 * 4]);
        __syncthreads();
#pragma unroll
        for (int kk = 0; kk < 16; kk++) {
            float4 a4 = *reinterpret_cast<const float4*>(&As[kk][ty * 4]);
            float4 b4 = *reinterpret_cast<const float4*>(&Bs[kk][tx * 4]);
            float a[4] = {a4.x, a4.y, a4.z, a4.w};
            float b[4] = {b4.x, b4.y, b4.z, b4.w};
#pragma unroll
            for (int i = 0; i < 4; i++)
#pragma unroll
                for (int j = 0; j < 4; j++)
                    acc[i][j] = fmaf(a[i], b[j], acc[i][j]);
        }
        __syncthreads();
    }
#pragma unroll
    for (int j = 0; j < 4; j++) {
        int col = nbase + tx * 4 + j;
        float bv = bias ? bias[col] : 0.0f;
#pragma unroll
        for (int i = 0; i < 4; i++) {
            int row = mbase + ty * 4 + i;
            C[(size_t)row * ldc + col] = acc[i][j] + bv;
        }
    }
}

// ================== generic fp16 mma GEMM (prologue) ======================
#define PLDH 24
#define PKT  48
#define PA_STAGE_B (128 * PLDH * 2)   // 6144 bytes
#define PSMEM_SZ (8 * PA_STAGE_B)     // 49152 bytes

__global__ void __launch_bounds__(256)
k_gemm_h(const __half* __restrict__ A, int lda,
         const __half* __restrict__ B, int ldb,
         const float* __restrict__ bias,
         __half* __restrict__ C, int ldc) {
    extern __shared__ char psm[];
    __half* Ash = reinterpret_cast<__half*>(psm);
    __half* Bsh = reinterpret_cast<__half*>(psm + 4 * PA_STAGE_B);
    const uint32_t sbA = smem_u32(Ash);
    const uint32_t sbB = smem_u32(Bsh);

    const int tid = threadIdx.x;
    const int lane = tid & 31, wid = tid >> 5;
    const int wm = wid & 3, wn = wid >> 2;
    const int qr = lane >> 2, qc = lane & 3;
    const int mb = blockIdx.x * 128;
    const int nb = blockIdx.y * 128;
    const int l_row = tid >> 1, l_ch = tid & 1;

    float cf[2][8][4];
#pragma unroll
    for (int mt = 0; mt < 2; mt++)
#pragma unroll
        for (int nt = 0; nt < 8; nt++)
#pragma unroll
            for (int r = 0; r < 4; r++) cf[mt][nt][r] = 0.0f;

#pragma unroll
    for (int p = 0; p < 3; p++) {
        const int k0 = p * 16;
        cpasync16(sbA + (uint32_t)(p * PA_STAGE_B + l_row * (PLDH * 2) + l_ch * 16),
                  &A[(size_t)(mb + l_row) * lda + k0 + l_ch * 8]);
        cpasync16(sbB + (uint32_t)(p * PA_STAGE_B + l_row * (PLDH * 2) + l_ch * 16),
                  &B[(size_t)(nb + l_row) * ldb + k0 + l_ch * 8]);
        CP_COMMIT();
    }

    for (int kt = 0; kt < PKT; kt++) {
        CP_WAIT2();
        __syncthreads();
        const int bi = kt & 3;
        const __half* Asb = Ash + bi * (128 * PLDH);
        const __half* Bsb = Bsh + bi * (128 * PLDH);
        uint32_t a[2][4];
#pragma unroll
        for (int mt = 0; mt < 2; mt++) {
            int rb = wm * 32 + mt * 16 + qr;
            a[mt][0] = *reinterpret_cast<const uint32_t*>(&Asb[rb * PLDH + 2 * qc]);
            a[mt][1] = *reinterpret_cast<const uint32_t*>(&Asb[(rb + 8) * PLDH + 2 * qc]);
            a[mt][2] = *reinterpret_cast<const uint32_t*>(&Asb[rb * PLDH + 2 * qc + 8]);
            a[mt][3] = *reinterpret_cast<const uint32_t*>(&Asb[(rb + 8) * PLDH + 2 * qc + 8]);
        }
#pragma unroll
        for (int nt = 0; nt < 8; nt++) {
            int ncol = wn * 64 + nt * 8 + qr;
            uint32_t b0 = *reinterpret_cast<const uint32_t*>(&Bsb[ncol * PLDH + 2 * qc]);
            uint32_t b1 = *reinterpret_cast<const uint32_t*>(&Bsb[ncol * PLDH + 2 * qc + 8]);
            mma_f16(cf[0][nt], a[0], b0, b1);
            mma_f16(cf[1][nt], a[1], b0, b1);
        }
        const int kn = kt + 3;
        if (kn < PKT) {
            const int st = kn & 3;
            const int k0 = kn * 16;
            cpasync16(sbA + (uint32_t)(st * PA_STAGE_B + l_row * (PLDH * 2) + l_ch * 16),
                      &A[(size_t)(mb + l_row) * lda + k0 + l_ch * 8]);
            cpasync16(sbB + (uint32_t)(st * PA_STAGE_B + l_row * (PLDH * 2) + l_ch * 16),
                      &B[(size_t)(nb + l_row) * ldb + k0 + l_ch * 8]);
        }
        CP_COMMIT();
    }

#pragma unroll
    for (int mt = 0; mt < 2; mt++)
#pragma unroll
        for (int nt = 0; nt < 8; nt++) {
            const int gcol = nb + wn * 64 + nt * 8 + 2 * qc;
            const int r0 = mb + wm * 32 + mt * 16 + qr;
            const float bv0 = bias ? bias[gcol] : 0.0f;
            const float bv1 = bias ? bias[gcol + 1] : 0.0f;
            *reinterpret_cast<__half2*>(&C[(size_t)r0 * ldc + gcol]) =
                __floats2half2_rn(cf[mt][nt][0] + bv0, cf[mt][nt][1] + bv1);
            *reinterpret_cast<__half2*>(&C[(size_t)(r0 + 8) * ldc + gcol]) =
                __floats2half2_rn(cf[mt][nt][2] + bv0, cf[mt][nt][3] + bv1);
        }
}

// ================== main fused fp16 mma kernel (persistent) ================
// 296 persistent blocks pop (w-tile 64, c) items (1024 total) from g_qhead.
// Block 256 threads (8 warps, 2m x 4n). BM=64, BN=128, BK=32, 3-stage
// cp.async + smem At prefetch; lb1[c] scale applied to A frags (HMUL2).
#define BM 64
#define BN 128
#define BK 32
#define NJT 6
#define KTILES 24
#define NITEMS (16 * C_NUM)         // (1024/64) * 64 = 1024
#define NBLOCKS 296
#define LDH 40                      // 32 + 8 pad halves; conflict-free
#define A_STAGE_B (BM * LDH * 2)    // 5120 bytes
#define B_STAGE_B (BN * LDH * 2)    // 10240 bytes
#define LDAT 136                    // At row: 128 + 8 pad halves

#define O_BS   (3 * A_STAGE_B)                 // 15360
#define O_ATS  (O_BS + 3 * B_STAGE_B)          // 46080
#define O_ALS  (O_ATS + BM * LDAT * 2)         // 63488
#define O_W2S  (O_ALS + H_DIM * 4)             // 66560
#define O_SCR  (O_W2S + 3 * H_DIM * 4)         // 75776
#define O_LBS  (O_SCR + BM * 3 * 4)            // 76544
#define SMEM_SZ (O_LBS + H_DIM * 2)            // 78080 bytes -> 2 blocks/SM

__global__ void __launch_bounds__(256, 2)
k_main_mma(const __half* __restrict__ t01h,   // (1024, 1536); t1 at col 768
           const __half* __restrict__ Bh,     // (768 j, 768 k) half(W1p^T)
           const __half* __restrict__ Ath,    // (1024, 768) half
           const float* __restrict__ lb,      // (64, 1536)
           const float* __restrict__ Al,      // (64, 768)
           const float* __restrict__ W2,      // (768, 3)
           const float* __restrict__ b2,
           float* __restrict__ out) {         // (1024, 64, 3)
    extern __shared__ char smc[];
    __half* Ash = reinterpret_cast<__half*>(smc);
    __half* Bsh = reinterpret_cast<__half*>(smc + O_BS);
    __half* Ats = reinterpret_cast<__half*>(smc + O_ATS);
    float* als = reinterpret_cast<float*>(smc + O_ALS);
    float* w2s = reinterpret_cast<float*>(smc + O_W2S);
    float* scr = reinterpret_cast<float*>(smc + O_SCR);
    __half* lbsh = reinterpret_cast<__half*>(smc + O_LBS);
    __shared__ int s_item;
    const uint32_t sbA = smem_u32(Ash);
    const uint32_t sbB = smem_u32(Bsh);
    const uint32_t sbT = smem_u32(Ats);

    const int tid = threadIdx.x;
    const int lane = tid & 31, wid = tid >> 5;
    const int wm = wid & 1, wn = wid >> 1;     // 2m x 4n warp layout
    const int qr = lane >> 2, qc = lane & 3;

    // c-independent table, loaded once
    for (int i = tid; i < 3 * H_DIM; i += 256) w2s[i] = W2[i];

    const float bb0 = __ldg(&b2[0]), bb1 = __ldg(&b2[1]), bb2 = __ldg(&b2[2]);
    const __half* A0 = t01h + H_DIM;           // t1 columns

    for (int safety = 0; safety < NITEMS + 8; safety++) {
        if (tid == 0) s_item = (int)atomicAdd(&g_qhead, 1u);
        __syncthreads();
        const int item = s_item;
        if (item >= NITEMS) break;
        const int wbase = (item & 15) * BM;
        const int c = item >> 4;

        // per-item c-dependent tables
        for (int i = tid; i < H_DIM; i += 256) {
            als[i] = Al[(size_t)c * H_DIM + i];
            lbsh[i] = __float2half(lb[(size_t)c * TH_DIM + H_DIM + i]);
        }
        for (int i = tid; i < BM * 3; i += 256) scr[i] = 0.0f;
        __syncthreads();

        const uint32_t* lbs2 = reinterpret_cast<const uint32_t*>(lbsh);

        float sc[4][3];
#pragma unroll
        for (int i = 0; i < 4; i++)
#pragma unroll
            for (int k = 0; k < 3; k++) sc[i][k] = 0.0f;

        for (int jt = 0; jt < NJT; jt++) {
            const int jb = jt * BN;
            float cf[2][4][4];
#pragma unroll
            for (int mt = 0; mt < 2; mt++)
#pragma unroll
                for (int nt = 0; nt < 4; nt++)
#pragma unroll
                    for (int r = 0; r < 4; r++) cf[mt][nt][r] = 0.0f;

            // ---- prologue: k-tiles 0..1 into stages 0..1 ----
#pragma unroll
            for (int p = 0; p < 2; p++) {
                const int k0 = p * BK;
                {   // A: 64 rows x 4 chunks = 256 -> 1/thread
                    int row = tid >> 2, ch = tid & 3;
                    cpasync16(sbA + (uint32_t)(p * A_STAGE_B + row * (LDH * 2) + ch * 16),
                              &A0[(size_t)(wbase + row) * TH_DIM + k0 + ch * 8]);
                }
#pragma unroll
                for (int i = 0; i < 2; i++) {   // B: 128 rows x 4 chunks = 512 -> 2/thread
                    int idx = tid + 256 * i;
                    int row = idx >> 2, ch = idx & 3;
                    cpasync16(sbB + (uint32_t)(p * B_STAGE_B + row * (LDH * 2) + ch * 16),
                              &Bh[(size_t)(jb + row) * H_DIM + k0 + ch * 8]);
                }
                CP_COMMIT();
            }

            for (int kt = 0; kt < KTILES; kt++) {
                CP_WAIT1();
                __syncthreads();
                const int bi = kt % 3;
                const __half* Asb = Ash + bi * (A_STAGE_B / 2);
                const __half* Bsb = Bsh + bi * (B_STAGE_B / 2);
#pragma unroll
                for (int ks = 0; ks < 2; ks++) {
                    const int ko = ks * 16;
                    const int kb2 = (kt * BK + ko) >> 1;
                    const uint32_t sA = lbs2[kb2 + qc];
                    const uint32_t sB = lbs2[kb2 + qc + 4];
                    uint32_t a[2][4];
#pragma unroll
                    for (int mt = 0; mt < 2; mt++) {
                        int rb = wm * 32 + mt * 16 + qr;
                        a[mt][0] = hmul2u(*reinterpret_cast<const uint32_t*>(&Asb[rb * LDH + ko + 2 * qc]), sA);
                        a[mt][1] = hmul2u(*reinterpret_cast<const uint32_t*>(&Asb[(rb + 8) * LDH + ko + 2 * qc]), sA);
                        a[mt][2] = hmul2u(*reinterpret_cast<const uint32_t*>(&Asb[rb * LDH + ko + 2 * qc + 8]), sB);
                        a[mt][3] = hmul2u(*reinterpret_cast<const uint32_t*>(&Asb[(rb + 8) * LDH + ko + 2 * qc + 8]), sB);
                    }
#pragma unroll
                    for (int nt = 0; nt < 4; nt++) {
                        int ncol = wn * 32 + nt * 8 + qr;
                        uint32_t b0 = *reinterpret_cast<const uint32_t*>(&Bsb[ncol * LDH + ko + 2 * qc]);
                        uint32_t b1 = *reinterpret_cast<const uint32_t*>(&Bsb[ncol * LDH + ko + 2 * qc + 8]);
                        mma_f16(cf[0][nt], a[0], b0, b1);
                        mma_f16(cf[1][nt], a[1], b0, b1);
                    }
                }
                // ---- stage k-tile kt+2; At tile rides groups of kts 0..3 ----
                const int kn = kt + 2;
                if (kn < KTILES) {
                    const int st = kn % 3;
                    const int k0 = kn * BK;
                    {
                        int row = tid >> 2, ch = tid & 3;
                        cpasync16(sbA + (uint32_t)(st * A_STAGE_B + row * (LDH * 2) + ch * 16),
                                  &A0[(size_t)(wbase + row) * TH_DIM + k0 + ch * 8]);
                    }
#pragma unroll
                    for (int i = 0; i < 2; i++) {
                        int idx = tid + 256 * i;
                        int row = idx >> 2, ch = idx & 3;
                        cpasync16(sbB + (uint32_t)(st * B_STAGE_B + row * (LDH * 2) + ch * 16),
                                  &Bh[(size_t)(jb + row) * H_DIM + k0 + ch * 8]);
                    }
                }
                if (kt < 4) {
                    // At j-tile: 64 rows x 16 chunks = 1024; 256 per kt
                    int cidx = tid + 256 * kt;
                    int row = cidx >> 4, ch = cidx & 15;
                    cpasync16(sbT + (uint32_t)(row * (LDAT * 2) + ch * 16),
                              &Ath[(size_t)(wbase + row) * H_DIM + jb + ch * 8]);
                }
                CP_COMMIT();
            }

            // ---- fused epilogue for this j-tile (At from smem) ----
#pragma unroll
            for (int mt = 0; mt < 2; mt++) {
#pragma unroll
                for (int nt = 0; nt < 4; nt++) {
                    const int lcol = wn * 32 + nt * 8 + 2 * qc;
                    const int gcol = jb + lcol;
                    const int lr0 = wm * 32 + mt * 16 + qr;
                    float2 at0 = __half22float2(
                        *reinterpret_cast<const __half2*>(&Ats[lr0 * LDAT + lcol]));
                    float2 at1 = __half22float2(
                        *reinterpret_cast<const __half2*>(&Ats[(lr0 + 8) * LDAT + lcol]));
                    const float al0 = als[gcol], al1 = als[gcol + 1];
                    const float wa0 = w2s[gcol * 3 + 0], wa1 = w2s[gcol * 3 + 1], wa2 = w2s[gcol * 3 + 2];
                    const float wb0 = w2s[gcol * 3 + 3], wb1 = w2s[gcol * 3 + 4], wb2 = w2s[gcol * 3 + 5];
                    const float h00 = fmaxf(cf[mt][nt][0] + at0.x + al0, 0.0f);
                    const float h01 = fmaxf(cf[mt][nt][1] + at0.y + al1, 0.0f);
                    const float h10 = fmaxf(cf[mt][nt][2] + at1.x + al0, 0.0f);
                    const float h11 = fmaxf(cf[mt][nt][3] + at1.y + al1, 0.0f);
                    sc[mt * 2 + 0][0] += h00 * wa0 + h01 * wb0;
                    sc[mt * 2 + 0][1] += h00 * wa1 + h01 * wb1;
                    sc[mt * 2 + 0][2] += h00 * wa2 + h01 * wb2;
                    sc[mt * 2 + 1][0] += h10 * wa0 + h11 * wb0;
                    sc[mt * 2 + 1][1] += h10 * wa1 + h11 * wb1;
                    sc[mt * 2 + 1][2] += h10 * wa2 + h11 * wb2;
                }
            }
            __syncthreads();   // Ats reads done before next j-tile overwrites
        }

        // ---- reduce over qc lanes, then across n-warps via shared atomics ----
#pragma unroll
        for (int i = 0; i < 4; i++)
#pragma unroll
            for (int k = 0; k < 3; k++) {
                float v = sc[i][k];
                v += __shfl_xor_sync(0xffffffffu, v, 1);
                v += __shfl_xor_sync(0xffffffffu, v, 2);
                sc[i][k] = v;
            }
        if (qc == 0) {
#pragma unroll
            for (int i = 0; i < 4; i++) {
                int rl = wm * 32 + (i >> 1) * 16 + (i & 1) * 8 + qr;
                atomicAdd(&scr[rl * 3 + 0], sc[i][0]);
                atomicAdd(&scr[rl * 3 + 1], sc[i][1]);
                atomicAdd(&scr[rl * 3 + 2], sc[i][2]);
            }
        }
        __syncthreads();
        if (tid < BM) {
            const int row = wbase + tid;
            float* o = &out[(size_t)row * (C_NUM * 3) + c * 3];
            o[0] = scr[tid * 3 + 0] + bb0;
            o[1] = scr[tid * 3 + 1] + bb1;
            o[2] = scr[tid * 3 + 2] + bb2;
        }
        __syncthreads();   // scr/als/lbsh reuse safe before next item
    }
}

// ---------------- launch ---------------------------------------------------
extern "C" void kernel_launch(void* const* d_in, const int* in_sizes, int n_in,
                              void* d_out, int out_size) {
    const float* tok_embs   = (const float*)d_in[0];   // (2048, 768)
    const int*   wmask      = (const int*)  d_in[1];   // (2048,)
    const float* label_embs = (const float*)d_in[3];   // (64, 768)
    const float* W_tok      = (const float*)d_in[4];   // (768, 1536)
    const float* b_tok      = (const float*)d_in[5];   // (1536,)
    const float* W_lab      = (const float*)d_in[6];   // (768, 1536)
    const float* b_lab      = (const float*)d_in[7];   // (1536,)
    const float* W1         = (const float*)d_in[8];   // (2304, 768)
    const float* b1         = (const float*)d_in[9];   // (768,)
    const float* W2         = (const float*)d_in[10];  // (768, 3)
    const float* b2         = (const float*)d_in[11];  // (3,)
    float* out = (float*)d_out;                        // (1024, 64, 3)

    float *lbp, *Al;
    __half *weh, *WtokT, *W1tT, *W1pTh, *t01h, *Ath;
    cudaGetSymbolAddress((void**)&lbp,   g_lb);
    cudaGetSymbolAddress((void**)&Ath,   g_Ath);
    cudaGetSymbolAddress((void**)&Al,    g_Al);
    cudaGetSymbolAddress((void**)&weh,   g_weh);
    cudaGetSymbolAddress((void**)&WtokT, g_WtokT);
    cudaGetSymbolAddress((void**)&W1tT,  g_W1tT);
    cudaGetSymbolAddress((void**)&W1pTh, g_W1pTh);
    cudaGetSymbolAddress((void**)&t01h,  g_t01h);

    // idempotent, deterministic — no static guards (harness rule)
    cudaFuncSetAttribute(k_main_mma, cudaFuncAttributeMaxDynamicSharedMemorySize, SMEM_SZ);
    cudaFuncSetAttribute(k_gemm_h, cudaFuncAttributeMaxDynamicSharedMemorySize, PSMEM_SZ);

    // 0) weight prep (independent): half transposes of W_tok, W1_t, W1_p
    k_transpose_h<<<dim3(TH_DIM / 32, H_DIM / 32), dim3(32, 8)>>>(
        W_tok, WtokT, H_DIM, TH_DIM);
    k_transpose_h<<<dim3(H_DIM / 32, H_DIM / 32), dim3(32, 8)>>>(
        W1, W1tT, H_DIM, H_DIM);
    k_transpose_h<<<dim3(H_DIM / 32, H_DIM / 32), dim3(32, 8)>>>(
        W1 + (size_t)2 * H_DIM * H_DIM, W1pTh, H_DIM, H_DIM);

    // 1) scatter pooling (last token index wins per word), half output
    k_init_winner<<<(W_NUM + 255) / 256, 256>>>();
    k_scatter<<<(L_TOK + 255) / 256, 256>>>(wmask);
    k_build_we_h<<<W_NUM, 256>>>(tok_embs);

    // 2) lb = label_embs @ W_lab + b_lab (64 x 1536, fp32 SIMT)
    k_gemm_bias<<<dim3(1, TH_DIM / 64), 256>>>(
        label_embs, H_DIM, W_lab, TH_DIM, b_lab, lbp, TH_DIM, H_DIM);

    // 3) t01h = half(weh @ W_tok + b_tok)   (1024 x 1536, fp16 mma)
    k_gemm_h<<<dim3(W_NUM / 128, TH_DIM / 128), 256, PSMEM_SZ>>>(
        weh, H_DIM, WtokT, H_DIM, b_tok, t01h, TH_DIM);

    // 4) Ath = half(t0h @ W1_t + b1)        (1024 x 768, fp16 mma)
    k_gemm_h<<<dim3(W_NUM / 128, H_DIM / 128), 256, PSMEM_SZ>>>(
        t01h, TH_DIM, W1tT, H_DIM, b1, Ath, H_DIM);

    // 5) Al = lb0 @ W1_l                    (64 x 768, fp32 SIMT)
    k_gemm_bias<<<dim3(1, H_DIM / 64), 256>>>(
        lbp, TH_DIM, W1 + (size_t)H_DIM * H_DIM, H_DIM, nullptr, Al, H_DIM, H_DIM);

    // 6) persistent fused fp16 mma prod-GEMM + relu + W2 -> scores
    k_main_mma<<<NBLOCKS, 256, SMEM_SZ>>>(
        t01h, W1pTh, Ath, lbp, Al, W2, b2, out);

    (void)in_sizes; (void)n_in; (void)out_size;
}

// round 17
// speedup vs baseline: 1.0812x; 1.0812x over previous
#include <cuda_runtime.h>
#include <cuda_fp16.h>
#include <cstdint>

// Problem constants (fixed shapes for GLiNERLinkerPooler_14671608283278)
#define L_TOK 2048
#define H_DIM 768
#define W_NUM 1024
#define C_NUM 64
#define TH_DIM 1536   // 2*H
// W1 is (2304, 768): rows [0,768)=W1_t, [768,1536)=W1_l, [1536,2304)=W1_p

// ---------------- device scratch (no allocations allowed) ----------------
__device__ int      g_winner[W_NUM];
__device__ __half   g_weh[W_NUM * H_DIM];
__device__ __half   g_WtokT[TH_DIM * H_DIM];      // half(W_tok^T) [n][k]
__device__ __half   g_W1tT[H_DIM * H_DIM];        // half(W1_t^T)  [n][k]
__device__ __half   g_W1pTh[H_DIM * H_DIM];       // half(W1_p^T)  [j][h]
__device__ __half   g_t01h[W_NUM * TH_DIM];       // half(t) [w][2H]
__device__ float    g_lb[C_NUM * TH_DIM];
__device__ __half   g_Ath[W_NUM * H_DIM];         // half(t0@W1_t + b1) [w][j]
__device__ float    g_Al[C_NUM * H_DIM];

// ---------------- helpers -------------------------------------------------
__device__ __forceinline__ void mma_f16(float* c, const uint32_t* a,
                                        uint32_t b0, uint32_t b1) {
    asm volatile(
        "mma.sync.aligned.m16n8k16.row.col.f32.f16.f16.f32 "
        "{%0,%1,%2,%3}, {%4,%5,%6,%7}, {%8,%9}, {%0,%1,%2,%3};"
        : "+f"(c[0]), "+f"(c[1]), "+f"(c[2]), "+f"(c[3])
        : "r"(a[0]), "r"(a[1]), "r"(a[2]), "r"(a[3]), "r"(b0), "r"(b1));
}
__device__ __forceinline__ uint32_t smem_u32(const void* p) {
    uint32_t a;
    asm("{ .reg .u64 t; cvta.to.shared.u64 t, %1; cvt.u32.u64 %0, t; }" : "=r"(a) : "l"(p));
    return a;
}
__device__ __forceinline__ void cpasync16(uint32_t dst, const void* src) {
    asm volatile("cp.async.cg.shared.global [%0], [%1], 16;" :: "r"(dst), "l"(src));
}
__device__ __forceinline__ uint32_t hmul2u(uint32_t a, uint32_t s) {
    __half2 r = __hmul2(*reinterpret_cast<__half2*>(&a), *reinterpret_cast<__half2*>(&s));
    return *reinterpret_cast<uint32_t*>(&r);
}
#define CP_COMMIT()  asm volatile("cp.async.commit_group;" ::: "memory")
#define CP_WAIT1()   asm volatile("cp.async.wait_group 1;" ::: "memory")
#define CP_WAIT2()   asm volatile("cp.async.wait_group 2;" ::: "memory")

// ---------------- merged weight prep + winner init ------------------------
// One launch does all three fp32->half transposes (src[K=768][N] -> dst[N][768])
// and initializes g_winner. Tiles: W_tok 48x24=1152, W1_t 24x24=576, W1_p 576.
__global__ void k_prep(const float* __restrict__ W_tok,
                       const float* __restrict__ W1) {
    __shared__ float tl[32][33];
    const int t = threadIdx.y * 32 + threadIdx.x;
    int b = blockIdx.x;
    if (b < 4) g_winner[b * 256 + t] = -1;

    const float* src;
    __half* dst;
    int nblk;
    if (b < 1152) {
        src = W_tok; dst = g_WtokT; nblk = TH_DIM / 32;
    } else if (b < 1728) {
        b -= 1152; src = W1; dst = g_W1tT; nblk = H_DIM / 32;
    } else {
        b -= 1728; src = W1 + (size_t)2 * H_DIM * H_DIM; dst = g_W1pTh; nblk = H_DIM / 32;
    }
    const int n0 = (b % nblk) * 32;
    const int k0 = (b / nblk) * 32;
    const int N = nblk * 32;
    for (int dy = threadIdx.y; dy < 32; dy += 8)
        tl[dy][threadIdx.x] = src[(size_t)(k0 + dy) * N + n0 + threadIdx.x];
    __syncthreads();
    for (int dy = threadIdx.y; dy < 32; dy += 8)
        dst[(size_t)(n0 + dy) * H_DIM + k0 + threadIdx.x] = __float2half(tl[threadIdx.x][dy]);
}

// ---------------- scatter pooling (last token index wins) ----------------
__global__ void k_scatter(const int* __restrict__ wmask) {
    int l = blockIdx.x * blockDim.x + threadIdx.x;
    if (l < L_TOK) {
        int v = wmask[l];
        if (v > 0 && v - 1 < W_NUM) atomicMax(&g_winner[v - 1], l);
    }
}
__global__ void k_build_we_h(const float* __restrict__ tok_embs) {
    int w = blockIdx.x;
    int src = g_winner[w];
    __half* dst = &g_weh[w * H_DIM];
    if (src >= 0) {
        const float* s = &tok_embs[(size_t)src * H_DIM];
        for (int h = threadIdx.x; h < H_DIM; h += blockDim.x) dst[h] = __float2half(s[h]);
    } else {
        for (int h = threadIdx.x; h < H_DIM; h += blockDim.x) dst[h] = __float2half(0.0f);
    }
}

// ---------------- SIMT fp32 GEMM (small label-side GEMMs only) ------------
__global__ void k_gemm_bias(const float* __restrict__ A, int lda,
                            const float* __restrict__ B, int ldb,
                            const float* __restrict__ bias,
                            float* __restrict__ C, int ldc, int K) {
    __shared__ float As[16][64];
    __shared__ float Bs[16][64];
    const int tid = threadIdx.x;
    const int tx = tid & 15;
    const int ty = tid >> 4;
    const int mbase = blockIdx.x * 64;
    const int nbase = blockIdx.y * 64;

    float acc[4][4] = {};
    const int lw = tid >> 2, lkq = tid & 3;
    const int lkk = tid >> 4, lj4 = tid & 15;

    for (int k0 = 0; k0 < K; k0 += 16) {
        float4 va = *reinterpret_cast<const float4*>(&A[(size_t)(mbase + lw) * lda + k0 + lkq * 4]);
        As[lkq * 4 + 0][lw] = va.x;
        As[lkq * 4 + 1][lw] = va.y;
        As[lkq * 4 + 2][lw] = va.z;
        As[lkq * 4 + 3][lw] = va.w;
        *reinterpret_cast<float4*>(&Bs[lkk][lj4 * 4]) =
            *reinterpret_cast<const float4*>(&B[(size_t)(k0 + lkk) * ldb + nbase + lj4 * 4]);
        __syncthreads();
#pragma unroll
        for (int kk = 0; kk < 16; kk++) {
            float4 a4 = *reinterpret_cast<const float4*>(&As[kk][ty * 4]);
            float4 b4 = *reinterpret_cast<const float4*>(&Bs[kk][tx * 4]);
            float a[4] = {a4.x, a4.y, a4.z, a4.w};
            float b[4] = {b4.x, b4.y, b4.z, b4.w};
#pragma unroll
            for (int i = 0; i < 4; i++)
#pragma unroll
                for (int j = 0; j < 4; j++)
                    acc[i][j] = fmaf(a[i], b[j], acc[i][j]);
        }
        __syncthreads();
    }
#pragma unroll
    for (int j = 0; j < 4; j++) {
        int col = nbase + tx * 4 + j;
        float bv = bias ? bias[col] : 0.0f;
#pragma unroll
        for (int i = 0; i < 4; i++) {
            int row = mbase + ty * 4 + i;
            C[(size_t)row * ldc + col] = acc[i][j] + bv;
        }
    }
}

// ================== generic fp16 mma GEMM (prologue) ======================
#define PLDH 24
#define PKT  48
#define PA_STAGE_B (128 * PLDH * 2)   // 6144 bytes
#define PSMEM_SZ (8 * PA_STAGE_B)     // 49152 bytes

__global__ void __launch_bounds__(256)
k_gemm_h(const __half* __restrict__ A, int lda,
         const __half* __restrict__ B, int ldb,
         const float* __restrict__ bias,
         __half* __restrict__ C, int ldc) {
    extern __shared__ char psm[];
    __half* Ash = reinterpret_cast<__half*>(psm);
    __half* Bsh = reinterpret_cast<__half*>(psm + 4 * PA_STAGE_B);
    const uint32_t sbA = smem_u32(Ash);
    const uint32_t sbB = smem_u32(Bsh);

    const int tid = threadIdx.x;
    const int lane = tid & 31, wid = tid >> 5;
    const int wm = wid & 3, wn = wid >> 2;
    const int qr = lane >> 2, qc = lane & 3;
    const int mb = blockIdx.x * 128;
    const int nb = blockIdx.y * 128;
    const int l_row = tid >> 1, l_ch = tid & 1;

    float cf[2][8][4];
#pragma unroll
    for (int mt = 0; mt < 2; mt++)
#pragma unroll
        for (int nt = 0; nt < 8; nt++)
#pragma unroll
            for (int r = 0; r < 4; r++) cf[mt][nt][r] = 0.0f;

#pragma unroll
    for (int p = 0; p < 3; p++) {
        const int k0 = p * 16;
        cpasync16(sbA + (uint32_t)(p * PA_STAGE_B + l_row * (PLDH * 2) + l_ch * 16),
                  &A[(size_t)(mb + l_row) * lda + k0 + l_ch * 8]);
        cpasync16(sbB + (uint32_t)(p * PA_STAGE_B + l_row * (PLDH * 2) + l_ch * 16),
                  &B[(size_t)(nb + l_row) * ldb + k0 + l_ch * 8]);
        CP_COMMIT();
    }

    for (int kt = 0; kt < PKT; kt++) {
        CP_WAIT2();
        __syncthreads();
        const int bi = kt & 3;
        const __half* Asb = Ash + bi * (128 * PLDH);
        const __half* Bsb = Bsh + bi * (128 * PLDH);
        uint32_t a[2][4];
#pragma unroll
        for (int mt = 0; mt < 2; mt++) {
            int rb = wm * 32 + mt * 16 + qr;
            a[mt][0] = *reinterpret_cast<const uint32_t*>(&Asb[rb * PLDH + 2 * qc]);
            a[mt][1] = *reinterpret_cast<const uint32_t*>(&Asb[(rb + 8) * PLDH + 2 * qc]);
            a[mt][2] = *reinterpret_cast<const uint32_t*>(&Asb[rb * PLDH + 2 * qc + 8]);
            a[mt][3] = *reinterpret_cast<const uint32_t*>(&Asb[(rb + 8) * PLDH + 2 * qc + 8]);
        }
#pragma unroll
        for (int nt = 0; nt < 8; nt++) {
            int ncol = wn * 64 + nt * 8 + qr;
            uint32_t b0 = *reinterpret_cast<const uint32_t*>(&Bsb[ncol * PLDH + 2 * qc]);
            uint32_t b1 = *reinterpret_cast<const uint32_t*>(&Bsb[ncol * PLDH + 2 * qc + 8]);
            mma_f16(cf[0][nt], a[0], b0, b1);
            mma_f16(cf[1][nt], a[1], b0, b1);
        }
        const int kn = kt + 3;
        if (kn < PKT) {
            const int st = kn & 3;
            const int k0 = kn * 16;
            cpasync16(sbA + (uint32_t)(st * PA_STAGE_B + l_row * (PLDH * 2) + l_ch * 16),
                      &A[(size_t)(mb + l_row) * lda + k0 + l_ch * 8]);
            cpasync16(sbB + (uint32_t)(st * PA_STAGE_B + l_row * (PLDH * 2) + l_ch * 16),
                      &B[(size_t)(nb + l_row) * ldb + k0 + l_ch * 8]);
        }
        CP_COMMIT();
    }

#pragma unroll
    for (int mt = 0; mt < 2; mt++)
#pragma unroll
        for (int nt = 0; nt < 8; nt++) {
            const int gcol = nb + wn * 64 + nt * 8 + 2 * qc;
            const int r0 = mb + wm * 32 + mt * 16 + qr;
            const float bv0 = bias ? bias[gcol] : 0.0f;
            const float bv1 = bias ? bias[gcol + 1] : 0.0f;
            *reinterpret_cast<__half2*>(&C[(size_t)r0 * ldc + gcol]) =
                __floats2half2_rn(cf[mt][nt][0] + bv0, cf[mt][nt][1] + bv1);
            *reinterpret_cast<__half2*>(&C[(size_t)(r0 + 8) * ldc + gcol]) =
                __floats2half2_rn(cf[mt][nt][2] + bv0, cf[mt][nt][3] + bv1);
        }
}

// ================== main fused fp16 mma kernel ============================
// Grid (8, 64). Block 256 (8 warps, 4m x 2n). BM=128, BN=128, BK=32,
// 3-stage cp.async + smem At prefetch. B = shared half(W1p^T) (L2-resident);
// per-c scale lb1 applied to A fragments in registers (HMUL2).
#define BM 128
#define BN 128
#define BK 32
#define NJT 6
#define KTILES 24
#define LDH 40                      // 32 + 8 pad halves; 80B rows, conflict-free
#define A_STAGE_B (BM * LDH * 2)    // 10240 bytes
#define LDAT 136                    // At row: 128 + 8 pad halves = 272 B (conflict-free)

#define O_BS   (3 * A_STAGE_B)                 // 30720
#define O_ATS  (O_BS + 3 * A_STAGE_B)          // 61440
#define O_ALS  (O_ATS + BM * LDAT * 2)         // 96256
#define O_W2S  (O_ALS + H_DIM * 4)             // 99328
#define O_SCR  (O_W2S + 3 * H_DIM * 4)         // 108544
#define O_LBS  (O_SCR + BM * 3 * 4)            // 110080
#define SMEM_SZ (O_LBS + H_DIM * 2)            // 111616 bytes -> 2 blocks/SM

__global__ void __launch_bounds__(256, 2)
k_main_mma(const __half* __restrict__ t01h,   // (1024, 1536); t1 at col 768
           const __half* __restrict__ Bh,     // (768 j, 768 k) half(W1p^T), shared
           const __half* __restrict__ Ath,    // (1024, 768) half
           const float* __restrict__ lb,      // (64, 1536)
           const float* __restrict__ Al,      // (64, 768)
           const float* __restrict__ W2,      // (768, 3)
           const float* __restrict__ b2,
           float* __restrict__ out) {         // (1024, 64, 3)
    extern __shared__ char smc[];
    __half* Ash = reinterpret_cast<__half*>(smc);
    __half* Bsh = reinterpret_cast<__half*>(smc + O_BS);
    __half* Ats = reinterpret_cast<__half*>(smc + O_ATS);
    float* als = reinterpret_cast<float*>(smc + O_ALS);
    float* w2s = reinterpret_cast<float*>(smc + O_W2S);
    float* scr = reinterpret_cast<float*>(smc + O_SCR);
    __half* lbsh = reinterpret_cast<__half*>(smc + O_LBS);
    const uint32_t sbA = smem_u32(Ash);
    const uint32_t sbB = smem_u32(Bsh);
    const uint32_t sbT = smem_u32(Ats);

    const int tid = threadIdx.x;
    const int lane = tid & 31, wid = tid >> 5;
    const int wm = wid & 3, wn = wid >> 2;
    const int qr = lane >> 2, qc = lane & 3;
    const int c = blockIdx.y;
    const int wbase = blockIdx.x * BM;

    for (int i = tid; i < H_DIM; i += 256) {
        als[i] = Al[c * H_DIM + i];
        lbsh[i] = __float2half(lb[(size_t)c * TH_DIM + H_DIM + i]);
    }
    for (int i = tid; i < 3 * H_DIM; i += 256) w2s[i] = W2[i];
    for (int i = tid; i < BM * 3; i += 256) scr[i] = 0.0f;
    __syncthreads();

    const uint32_t* lbs2 = reinterpret_cast<const uint32_t*>(lbsh);
    const __half* A0 = t01h + H_DIM;    // t1 columns

    float sc[4][3];
#pragma unroll
    for (int i = 0; i < 4; i++)
#pragma unroll
        for (int k = 0; k < 3; k++) sc[i][k] = 0.0f;

    for (int jt = 0; jt < NJT; jt++) {
        const int jb = jt * BN;
        float cf[2][8][4];
#pragma unroll
        for (int mt = 0; mt < 2; mt++)
#pragma unroll
            for (int nt = 0; nt < 8; nt++)
#pragma unroll
                for (int r = 0; r < 4; r++) cf[mt][nt][r] = 0.0f;

        // ---- prologue: k-tiles 0..1 into stages 0..1 (2 chunks/thread/matrix) ----
#pragma unroll
        for (int p = 0; p < 2; p++) {
            const int k0 = p * BK;
#pragma unroll
            for (int i = 0; i < 2; i++) {
                int idx = tid + 256 * i;
                int row = idx >> 2, ch = idx & 3;
                cpasync16(sbA + (uint32_t)(p * A_STAGE_B + row * (LDH * 2) + ch * 16),
                          &A0[(size_t)(wbase + row) * TH_DIM + k0 + ch * 8]);
                cpasync16(sbB + (uint32_t)(p * A_STAGE_B + row * (LDH * 2) + ch * 16),
                          &Bh[(size_t)(jb + row) * H_DIM + k0 + ch * 8]);
            }
            CP_COMMIT();
        }

        for (int kt = 0; kt < KTILES; kt++) {
            CP_WAIT1();
            __syncthreads();
            const int bi = kt % 3;
            const __half* Asb = Ash + bi * (A_STAGE_B / 2);
            const __half* Bsb = Bsh + bi * (A_STAGE_B / 2);
#pragma unroll
            for (int ks = 0; ks < 2; ks++) {
                const int ko = ks * 16;
                const int kb2 = (kt * BK + ko) >> 1;
                const uint32_t sA = lbs2[kb2 + qc];
                const uint32_t sB = lbs2[kb2 + qc + 4];
                uint32_t a[2][4];
#pragma unroll
                for (int mt = 0; mt < 2; mt++) {
                    int rb = wm * 32 + mt * 16 + qr;
                    a[mt][0] = hmul2u(*reinterpret_cast<const uint32_t*>(&Asb[rb * LDH + ko + 2 * qc]), sA);
                    a[mt][1] = hmul2u(*reinterpret_cast<const uint32_t*>(&Asb[(rb + 8) * LDH + ko + 2 * qc]), sA);
                    a[mt][2] = hmul2u(*reinterpret_cast<const uint32_t*>(&Asb[rb * LDH + ko + 2 * qc + 8]), sB);
                    a[mt][3] = hmul2u(*reinterpret_cast<const uint32_t*>(&Asb[(rb + 8) * LDH + ko + 2 * qc + 8]), sB);
                }
#pragma unroll
                for (int nt = 0; nt < 8; nt++) {
                    int ncol = wn * 64 + nt * 8 + qr;
                    uint32_t b0 = *reinterpret_cast<const uint32_t*>(&Bsb[ncol * LDH + ko + 2 * qc]);
                    uint32_t b1 = *reinterpret_cast<const uint32_t*>(&Bsb[ncol * LDH + ko + 2 * qc + 8]);
                    mma_f16(cf[0][nt], a[0], b0, b1);
                    mma_f16(cf[1][nt], a[1], b0, b1);
                }
            }
            // ---- issue k-tile kt+2 + one At chunk per thread (kts 0..7) ----
            const int kn = kt + 2;
            if (kn < KTILES) {
                const int st = kn % 3;
                const int k0 = kn * BK;
#pragma unroll
                for (int i = 0; i < 2; i++) {
                    int idx = tid + 256 * i;
                    int row = idx >> 2, ch = idx & 3;
                    cpasync16(sbA + (uint32_t)(st * A_STAGE_B + row * (LDH * 2) + ch * 16),
                              &A0[(size_t)(wbase + row) * TH_DIM + k0 + ch * 8]);
                    cpasync16(sbB + (uint32_t)(st * A_STAGE_B + row * (LDH * 2) + ch * 16),
                              &Bh[(size_t)(jb + row) * H_DIM + k0 + ch * 8]);
                }
            }
            if (kt < 8) {
                // At j-tile: 128 rows x 16 chunks of 16B; 256 chunks per kt
                int cidx = tid + 256 * kt;
                int row = cidx >> 4, ch = cidx & 15;
                cpasync16(sbT + (uint32_t)(row * (LDAT * 2) + ch * 16),
                          &Ath[(size_t)(wbase + row) * H_DIM + jb + ch * 8]);
            }
            CP_COMMIT();
        }

        // ---- fused epilogue for this j-tile (At from smem) ----
#pragma unroll
        for (int mt = 0; mt < 2; mt++) {
#pragma unroll
            for (int nt = 0; nt < 8; nt++) {
                const int lcol = wn * 64 + nt * 8 + 2 * qc;
                const int gcol = jb + lcol;
                const int lr0 = wm * 32 + mt * 16 + qr;
                float2 at0 = __half22float2(
                    *reinterpret_cast<const __half2*>(&Ats[lr0 * LDAT + lcol]));
                float2 at1 = __half22float2(
                    *reinterpret_cast<const __half2*>(&Ats[(lr0 + 8) * LDAT + lcol]));
                const float al0 = als[gcol], al1 = als[gcol + 1];
                const float wa0 = w2s[gcol * 3 + 0], wa1 = w2s[gcol * 3 + 1], wa2 = w2s[gcol * 3 + 2];
                const float wb0 = w2s[gcol * 3 + 3], wb1 = w2s[gcol * 3 + 4], wb2 = w2s[gcol * 3 + 5];
                const float h00 = fmaxf(cf[mt][nt][0] + at0.x + al0, 0.0f);
                const float h01 = fmaxf(cf[mt][nt][1] + at0.y + al1, 0.0f);
                const float h10 = fmaxf(cf[mt][nt][2] + at1.x + al0, 0.0f);
                const float h11 = fmaxf(cf[mt][nt][3] + at1.y + al1, 0.0f);
                sc[mt * 2 + 0][0] += h00 * wa0 + h01 * wb0;
                sc[mt * 2 + 0][1] += h00 * wa1 + h01 * wb1;
                sc[mt * 2 + 0][2] += h00 * wa2 + h01 * wb2;
                sc[mt * 2 + 1][0] += h10 * wa0 + h11 * wb0;
                sc[mt * 2 + 1][1] += h10 * wa1 + h11 * wb1;
                sc[mt * 2 + 1][2] += h10 * wa2 + h11 * wb2;
            }
        }
        __syncthreads();   // all epilogue reads of Ats done before next j-tile overwrites
    }

    // ---- reduce over qc lanes, then across n-warps via shared atomics ----
#pragma unroll
    for (int i = 0; i < 4; i++)
#pragma unroll
        for (int k = 0; k < 3; k++) {
            float v = sc[i][k];
            v += __shfl_xor_sync(0xffffffffu, v, 1);
            v += __shfl_xor_sync(0xffffffffu, v, 2);
            sc[i][k] = v;
        }
    if (qc == 0) {
#pragma unroll
        for (int i = 0; i < 4; i++) {
            int rl = wm * 32 + (i >> 1) * 16 + (i & 1) * 8 + qr;
            atomicAdd(&scr[rl * 3 + 0], sc[i][0]);
            atomicAdd(&scr[rl * 3 + 1], sc[i][1]);
            atomicAdd(&scr[rl * 3 + 2], sc[i][2]);
        }
    }
    __syncthreads();
    if (tid < BM) {
        const int row = wbase + tid;
        float* o = &out[(size_t)row * (C_NUM * 3) + c * 3];
        o[0] = scr[tid * 3 + 0] + __ldg(&b2[0]);
        o[1] = scr[tid * 3 + 1] + __ldg(&b2[1]);
        o[2] = scr[tid * 3 + 2] + __ldg(&b2[2]);
    }
}

// ---------------- launch ---------------------------------------------------
extern "C" void kernel_launch(void* const* d_in, const int* in_sizes, int n_in,
                              void* d_out, int out_size) {
    const float* tok_embs   = (const float*)d_in[0];   // (2048, 768)
    const int*   wmask      = (const int*)  d_in[1];   // (2048,)
    const float* label_embs = (const float*)d_in[3];   // (64, 768)
    const float* W_tok      = (const float*)d_in[4];   // (768, 1536)
    const float* b_tok      = (const float*)d_in[5];   // (1536,)
    const float* W_lab      = (const float*)d_in[6];   // (768, 1536)
    const float* b_lab      = (const float*)d_in[7];   // (1536,)
    const float* W1         = (const float*)d_in[8];   // (2304, 768)
    const float* b1         = (const float*)d_in[9];   // (768,)
    const float* W2         = (const float*)d_in[10];  // (768, 3)
    const float* b2         = (const float*)d_in[11];  // (3,)
    float* out = (float*)d_out;                        // (1024, 64, 3)

    float *lbp, *Al;
    __half *weh, *WtokT, *W1tT, *W1pTh, *t01h, *Ath;
    cudaGetSymbolAddress((void**)&lbp,   g_lb);
    cudaGetSymbolAddress((void**)&Ath,   g_Ath);
    cudaGetSymbolAddress((void**)&Al,    g_Al);
    cudaGetSymbolAddress((void**)&weh,   g_weh);
    cudaGetSymbolAddress((void**)&WtokT, g_WtokT);
    cudaGetSymbolAddress((void**)&W1tT,  g_W1tT);
    cudaGetSymbolAddress((void**)&W1pTh, g_W1pTh);
    cudaGetSymbolAddress((void**)&t01h,  g_t01h);

    // idempotent, deterministic — no static guards (harness rule)
    cudaFuncSetAttribute(k_main_mma, cudaFuncAttributeMaxDynamicSharedMemorySize, SMEM_SZ);
    cudaFuncSetAttribute(k_gemm_h, cudaFuncAttributeMaxDynamicSharedMemorySize, PSMEM_SZ);

    // 0) merged weight prep (3 transposes) + winner init, one launch
    k_prep<<<2304, dim3(32, 8)>>>(W_tok, W1);

    // 1) scatter pooling (last token index wins per word), half output
    k_scatter<<<(L_TOK + 255) / 256, 256>>>(wmask);
    k_build_we_h<<<W_NUM, 256>>>(tok_embs);

    // 2) lb = label_embs @ W_lab + b_lab (64 x 1536, fp32 SIMT)
    k_gemm_bias<<<dim3(1, TH_DIM / 64), 256>>>(
        label_embs, H_DIM, W_lab, TH_DIM, b_lab, lbp, TH_DIM, H_DIM);

    // 3) t01h = half(weh @ W_tok + b_tok)   (1024 x 1536, fp16 mma)
    k_gemm_h<<<dim3(W_NUM / 128, TH_DIM / 128), 256, PSMEM_SZ>>>(
        weh, H_DIM, WtokT, H_DIM, b_tok, t01h, TH_DIM);

    // 4) Ath = half(t0h @ W1_t + b1)        (1024 x 768, fp16 mma)
    k_gemm_h<<<dim3(W_NUM / 128, H_DIM / 128), 256, PSMEM_SZ>>>(
        t01h, TH_DIM, W1tT, H_DIM, b1, Ath, H_DIM);

    // 5) Al = lb0 @ W1_l                    (64 x 768, fp32 SIMT)
    k_gemm_bias<<<dim3(1, H_DIM / 64), 256>>>(
        lbp, TH_DIM, W1 + (size_t)H_DIM * H_DIM, H_DIM, nullptr, Al, H_DIM, H_DIM);

    // 6) fused fp16 mma prod-GEMM + relu + W2 contraction -> scores
    k_main_mma<<<dim3(W_NUM / BM, C_NUM), 256, SMEM_SZ>>>(
        t01h, W1pTh, Ath, lbp, Al, W2, b2, out);

    (void)in_sizes; (void)n_in; (void)out_size;
}